// round 4
// baseline (speedup 1.0000x reference)
#include <cuda_runtime.h>
#include <cuda_fp16.h>
#include <cstdint>

// Problem constants
#define M_DIM 8192
#define N_DIM 4096
#define K_DIM 4096
#define RANK  16

// GEMM tiling: block 128x256, 16 warps, warp tile 64x32
#define BM 128
#define BN 256
#define BK 32                        // fp16 elems per k-tile
#define NT (K_DIM / BK)              // 128 k-iterations
#define NSTAGE 4
#define RS 40                        // smem row stride in halves (32 + 8 pad)
#define RSB (RS * 2)                 // 80 bytes
#define A_ST_BYTES (BM * RSB)        // 10240
#define B_ST_BYTES (BN * RSB)        // 20480
#define STAGE_BYTES (A_ST_BYTES + B_ST_BYTES)   // 30720
#define SMEM_TOTAL (NSTAGE * STAGE_BYTES)       // 122880

// Pre-converted fp16 operands (device globals: allocation-free rule)
__device__ __half g_xh[(size_t)M_DIM * K_DIM];
__device__ __half g_wh[(size_t)N_DIM * K_DIM];

// ---------------------------------------------------------------------------
// PTX helpers (baseline ISA only: sm_80/75 features)
// ---------------------------------------------------------------------------
__device__ __forceinline__ uint32_t smem_to_u32(const void* p) {
    uint32_t a;
    asm("{ .reg .u64 t; cvta.to.shared.u64 t, %1; cvt.u32.u64 %0, t; }" : "=r"(a) : "l"(p));
    return a;
}
#define CP_ASYNC16(dst, src) \
    asm volatile("cp.async.cg.shared.global [%0], [%1], 16;" :: "r"(dst), "l"(src))
#define CP_COMMIT() asm volatile("cp.async.commit_group;")
#define CP_WAIT(n)  asm volatile("cp.async.wait_group %0;" :: "n"(n))

#define LDSM_X4(r, addr) \
    asm volatile("ldmatrix.sync.aligned.m8n8.x4.shared.b16 {%0,%1,%2,%3}, [%4];" \
                 : "=r"((r)[0]), "=r"((r)[1]), "=r"((r)[2]), "=r"((r)[3]) : "r"(addr))

#define MMA_F16(d, a, b0, b1) \
    asm volatile("mma.sync.aligned.m16n8k16.row.col.f32.f16.f16.f32 " \
                 "{%0,%1,%2,%3}, {%4,%5,%6,%7}, {%8,%9}, {%0,%1,%2,%3};" \
                 : "+f"((d)[0]), "+f"((d)[1]), "+f"((d)[2]), "+f"((d)[3]) \
                 : "r"((a)[0]), "r"((a)[1]), "r"((a)[2]), "r"((a)[3]), "r"(b0), "r"(b1))

// ---------------------------------------------------------------------------
// Kernel 1 (merged prologue): convert x -> fp16 AND fold W_eff -> fp16.
// Blocks [0, XBLK) handle x; blocks [XBLK, XBLK+WBLK) handle W_eff.
// ---------------------------------------------------------------------------
#define XBLK ((int)(((size_t)M_DIM * K_DIM) / 4 / 256))   // 32768
#define WBLK ((int)(((size_t)N_DIM * K_DIM) / 4 / 256))   // 16384

__global__ void prologue_kernel(const float* __restrict__ x,
                                const float* __restrict__ W,
                                const float* __restrict__ w1a,
                                const float* __restrict__ w1b,
                                const float* __restrict__ w2a,
                                const float* __restrict__ w2b,
                                const float* __restrict__ scalar) {
    if (blockIdx.x < XBLK) {
        size_t i = (size_t)(blockIdx.x * 256 + threadIdx.x) * 4;
        float4 v = *(const float4*)(x + i);
        __half2* o = (__half2*)(g_xh + i);
        o[0] = __floats2half2_rn(v.x, v.y);
        o[1] = __floats2half2_rn(v.z, v.w);
    } else {
        size_t idx = (size_t)((blockIdx.x - XBLK) * 256 + threadIdx.x) * 4;
        int o = (int)(idx >> 12);
        int i = (int)(idx & 4095);
        float4 s1 = {0.f, 0.f, 0.f, 0.f};
        float4 s2 = {0.f, 0.f, 0.f, 0.f};
#pragma unroll
        for (int r = 0; r < RANK; ++r) {
            float a1 = w1a[o * RANK + r];
            float a2 = w2a[o * RANK + r];
            float4 b1 = *(const float4*)(w1b + (size_t)r * K_DIM + i);
            float4 b2 = *(const float4*)(w2b + (size_t)r * K_DIM + i);
            s1.x += a1 * b1.x; s1.y += a1 * b1.y; s1.z += a1 * b1.z; s1.w += a1 * b1.w;
            s2.x += a2 * b2.x; s2.y += a2 * b2.y; s2.z += a2 * b2.z; s2.w += a2 * b2.w;
        }
        float sc = scalar[0];
        float4 w = *(const float4*)(W + idx);
        __half2* out = (__half2*)(g_wh + idx);
        out[0] = __floats2half2_rn(w.x + s1.x * s2.x * sc, w.y + s1.y * s2.y * sc);
        out[1] = __floats2half2_rn(w.z + s1.z * s2.z * sc, w.w + s1.w * s2.w * sc);
    }
}

// ---------------------------------------------------------------------------
// Kernel 2: Y[M,N] = Xh[M,K] @ Wh[N,K]^T + bias
// 512 threads (16 warps), warp grid 2(M) x 8(N), warp tile 64x32.
// ---------------------------------------------------------------------------
__global__ void __launch_bounds__(512, 1)
gemm_f16_kernel(const float* __restrict__ bias, float* __restrict__ Y) {
    extern __shared__ char smem[];
    const uint32_t sb0 = smem_to_u32(smem);
    const int tid = threadIdx.x;
    const int l = tid & 31;
    const int warp = tid >> 5;
    const int wm = warp & 1;     // 2 warps along M (64 rows)
    const int wn = warp >> 1;    // 8 warps along N (32 cols)

    // tile coords with 8-row supertile swizzle for L2 reuse
    const int bid = blockIdx.x;                 // 0..1023
    const int sbt = bid >> 7;
    const int rr = bid & 127;
    const int m0 = ((sbt << 3) + (rr & 7)) * BM;
    const int n0 = (rr >> 3) * BN;

    const __half* Xg = g_xh + (size_t)m0 * K_DIM;
    const __half* Wg = g_wh + (size_t)n0 * K_DIM;

    // gmem->smem cp.async mapping: 512 threads -> (row 0..127, 16B chunk 0..3)
    const int arow = tid >> 2;           // 0..127
    const int achk = tid & 3;            // 16B chunks (8 halves)

    // ldmatrix lane address components
    const uint32_t lrow = l & 15;
    const uint32_t lkof = (uint32_t)(l >> 4) * 16;   // bytes (k8 half-tile)
    const uint32_t a_lane = (uint32_t)(wm * 64 + lrow) * RSB + lkof;
    const uint32_t b_lane = A_ST_BYTES + (uint32_t)(wn * 32 + lrow) * RSB + lkof;

    float acc[4][4][4];
#pragma unroll
    for (int a = 0; a < 4; ++a)
#pragma unroll
        for (int b = 0; b < 4; ++b)
#pragma unroll
            for (int c = 0; c < 4; ++c) acc[a][b][c] = 0.f;

    // ---- pipeline prologue ----
#pragma unroll
    for (int s = 0; s < NSTAGE - 1; ++s) {
        const uint32_t sa = sb0 + s * STAGE_BYTES;
        CP_ASYNC16(sa + (uint32_t)arow * RSB + achk * 16,
                   Xg + (size_t)arow * K_DIM + s * BK + achk * 8);
#pragma unroll
        for (int i = 0; i < 2; ++i)
            CP_ASYNC16(sa + A_ST_BYTES + (uint32_t)(arow + i * 128) * RSB + achk * 16,
                       Wg + (size_t)(arow + i * 128) * K_DIM + s * BK + achk * 8);
        CP_COMMIT();
    }
    CP_WAIT(NSTAGE - 2);
    __syncthreads();

    // ---- main loop ----
    for (int kt = 0; kt < NT; ++kt) {
        const int cur = kt & (NSTAGE - 1);
        const int nk = kt + NSTAGE - 1;
        if (nk < NT) {
            const uint32_t sa = sb0 + (nk & (NSTAGE - 1)) * STAGE_BYTES;
            CP_ASYNC16(sa + (uint32_t)arow * RSB + achk * 16,
                       Xg + (size_t)arow * K_DIM + nk * BK + achk * 8);
#pragma unroll
            for (int i = 0; i < 2; ++i)
                CP_ASYNC16(sa + A_ST_BYTES + (uint32_t)(arow + i * 128) * RSB + achk * 16,
                           Wg + (size_t)(arow + i * 128) * K_DIM + nk * BK + achk * 8);
        }
        CP_COMMIT();

        const uint32_t sa = sb0 + cur * STAGE_BYTES;
#pragma unroll
        for (int ks = 0; ks < 2; ++ks) {            // two k16 steps per BK=32
            uint32_t afr[4][4], bfr[2][4];
#pragma unroll
            for (int mi = 0; mi < 4; ++mi)
                LDSM_X4(afr[mi], sa + a_lane + (uint32_t)mi * 16 * RSB + ks * 32);
#pragma unroll
            for (int bi = 0; bi < 2; ++bi)
                LDSM_X4(bfr[bi], sa + b_lane + (uint32_t)bi * 16 * RSB + ks * 32);
#pragma unroll
            for (int mi = 0; mi < 4; ++mi)
#pragma unroll
                for (int bi = 0; bi < 2; ++bi) {
                    MMA_F16(acc[mi][2 * bi],     afr[mi], bfr[bi][0], bfr[bi][2]);
                    MMA_F16(acc[mi][2 * bi + 1], afr[mi], bfr[bi][1], bfr[bi][3]);
                }
        }
        CP_WAIT(NSTAGE - 2);
        __syncthreads();
    }

    // ---- epilogue: add bias, write fp32 ----
    const int g = l >> 2;
    const int t = l & 3;
#pragma unroll
    for (int mi = 0; mi < 4; ++mi) {
        const int row0 = m0 + wm * 64 + mi * 16 + g;
        float* y0 = Y + (size_t)row0 * N_DIM;
#pragma unroll
        for (int ni = 0; ni < 4; ++ni) {
            const int col = n0 + wn * 32 + ni * 8 + 2 * t;
            const float2 bv = *(const float2*)(bias + col);
            float2 o0, o1;
            o0.x = acc[mi][ni][0] + bv.x;  o0.y = acc[mi][ni][1] + bv.y;
            o1.x = acc[mi][ni][2] + bv.x;  o1.y = acc[mi][ni][3] + bv.y;
            *(float2*)(y0 + col) = o0;
            *(float2*)(y0 + (size_t)8 * N_DIM + col) = o1;   // rows g+8
        }
    }
}

// ---------------------------------------------------------------------------
extern "C" void kernel_launch(void* const* d_in, const int* in_sizes, int n_in,
                              void* d_out, int out_size) {
    const float* x      = (const float*)d_in[0];
    const float* W      = (const float*)d_in[1];
    const float* bias   = (const float*)d_in[2];
    const float* w1a    = (const float*)d_in[3];
    const float* w1b    = (const float*)d_in[4];
    const float* w2a    = (const float*)d_in[5];
    const float* w2b    = (const float*)d_in[6];
    const float* scalar = (const float*)d_in[7];
    float* y = (float*)d_out;

    prologue_kernel<<<XBLK + WBLK, 256>>>(x, W, w1a, w1b, w2a, w2b, scalar);

    cudaFuncSetAttribute(gemm_f16_kernel,
                         cudaFuncAttributeMaxDynamicSharedMemorySize, SMEM_TOTAL);
    const int nblocks = (M_DIM / BM) * (N_DIM / BN);   // 64 * 16 = 1024
    gemm_f16_kernel<<<nblocks, 512, SMEM_TOTAL>>>(bias, y);
}

// round 5
// speedup vs baseline: 1.9431x; 1.9431x over previous
#include <cuda_runtime.h>
#include <cuda_fp16.h>
#include <cstdint>

// Problem constants
#define M_DIM 8192
#define N_DIM 4096
#define K_DIM 4096
#define RANK  16

// GEMM tiling: block 128x256, 8 warps, warp tile 64x64
#define BM 128
#define BN 256
#define BK 32                        // fp16 elems per k-tile
#define NT (K_DIM / BK)              // 128 k-iterations
#define NSTAGE 4
#define RS 40                        // smem row stride in halves (32 + 8 pad)
#define RSB (RS * 2)                 // 80 bytes
#define A_ST_BYTES (BM * RSB)        // 10240
#define B_ST_BYTES (BN * RSB)        // 20480
#define STAGE_BYTES (A_ST_BYTES + B_ST_BYTES)   // 30720
#define SMEM_TOTAL (NSTAGE * STAGE_BYTES)       // 122880

// Pre-converted fp16 operands (device globals: allocation-free rule)
__device__ __half g_xh[(size_t)M_DIM * K_DIM];
__device__ __half g_wh[(size_t)N_DIM * K_DIM];

// ---------------------------------------------------------------------------
// PTX helpers (baseline ISA only)
// ---------------------------------------------------------------------------
__device__ __forceinline__ uint32_t smem_to_u32(const void* p) {
    uint32_t a;
    asm("{ .reg .u64 t; cvta.to.shared.u64 t, %1; cvt.u32.u64 %0, t; }" : "=r"(a) : "l"(p));
    return a;
}
#define CP_ASYNC16(dst, src) \
    asm volatile("cp.async.cg.shared.global [%0], [%1], 16;" :: "r"(dst), "l"(src))
#define CP_COMMIT() asm volatile("cp.async.commit_group;")
#define CP_WAIT(n)  asm volatile("cp.async.wait_group %0;" :: "n"(n))

#define LDSM_X4(r, addr) \
    asm volatile("ldmatrix.sync.aligned.m8n8.x4.shared.b16 {%0,%1,%2,%3}, [%4];" \
                 : "=r"((r)[0]), "=r"((r)[1]), "=r"((r)[2]), "=r"((r)[3]) : "r"(addr))

#define MMA_F16(d, a, b0, b1) \
    asm volatile("mma.sync.aligned.m16n8k16.row.col.f32.f16.f16.f32 " \
                 "{%0,%1,%2,%3}, {%4,%5,%6,%7}, {%8,%9}, {%0,%1,%2,%3};" \
                 : "+f"((d)[0]), "+f"((d)[1]), "+f"((d)[2]), "+f"((d)[3]) \
                 : "r"((a)[0]), "r"((a)[1]), "r"((a)[2]), "r"((a)[3]), "r"(b0), "r"(b1))

// ---------------------------------------------------------------------------
// Kernel 1 (merged prologue): convert x -> fp16 AND fold W_eff -> fp16.
// ---------------------------------------------------------------------------
#define XBLK ((int)(((size_t)M_DIM * K_DIM) / 4 / 256))   // 32768
#define WBLK ((int)(((size_t)N_DIM * K_DIM) / 4 / 256))   // 16384

__global__ void prologue_kernel(const float* __restrict__ x,
                                const float* __restrict__ W,
                                const float* __restrict__ w1a,
                                const float* __restrict__ w1b,
                                const float* __restrict__ w2a,
                                const float* __restrict__ w2b,
                                const float* __restrict__ scalar) {
    if (blockIdx.x < XBLK) {
        size_t i = (size_t)(blockIdx.x * 256 + threadIdx.x) * 4;
        float4 v = *(const float4*)(x + i);
        __half2* o = (__half2*)(g_xh + i);
        o[0] = __floats2half2_rn(v.x, v.y);
        o[1] = __floats2half2_rn(v.z, v.w);
    } else {
        size_t idx = (size_t)((blockIdx.x - XBLK) * 256 + threadIdx.x) * 4;
        int o = (int)(idx >> 12);
        int i = (int)(idx & 4095);
        float4 s1 = {0.f, 0.f, 0.f, 0.f};
        float4 s2 = {0.f, 0.f, 0.f, 0.f};
#pragma unroll
        for (int r = 0; r < RANK; ++r) {
            float a1 = w1a[o * RANK + r];
            float a2 = w2a[o * RANK + r];
            float4 b1 = *(const float4*)(w1b + (size_t)r * K_DIM + i);
            float4 b2 = *(const float4*)(w2b + (size_t)r * K_DIM + i);
            s1.x += a1 * b1.x; s1.y += a1 * b1.y; s1.z += a1 * b1.z; s1.w += a1 * b1.w;
            s2.x += a2 * b2.x; s2.y += a2 * b2.y; s2.z += a2 * b2.z; s2.w += a2 * b2.w;
        }
        float sc = scalar[0];
        float4 w = *(const float4*)(W + idx);
        __half2* out = (__half2*)(g_wh + idx);
        out[0] = __floats2half2_rn(w.x + s1.x * s2.x * sc, w.y + s1.y * s2.y * sc);
        out[1] = __floats2half2_rn(w.z + s1.z * s2.z * sc, w.w + s1.w * s2.w * sc);
    }
}

// ---------------------------------------------------------------------------
// Kernel 2: Y = Xh @ Wh^T + bias. 256 threads, warp grid 2(M) x 4(N),
// warp tile 64x64, register-double-buffered fragments.
// ---------------------------------------------------------------------------
__global__ void __launch_bounds__(256, 1)
gemm_f16_kernel(const float* __restrict__ bias, float* __restrict__ Y) {
    extern __shared__ char smem[];
    const uint32_t sb0 = smem_to_u32(smem);
    const int tid = threadIdx.x;
    const int l = tid & 31;
    const int warp = tid >> 5;
    const int wm = warp & 1;     // 2 warps along M (64 rows)
    const int wn = warp >> 1;    // 4 warps along N (64 cols)

    // tile coords with 8-row supertile swizzle for L2 reuse
    const int bid = blockIdx.x;
    const int sbt = bid >> 7;
    const int rr = bid & 127;
    const int m0 = ((sbt << 3) + (rr & 7)) * BM;
    const int n0 = (rr >> 3) * BN;

    const __half* Xg = g_xh + (size_t)m0 * K_DIM;
    const __half* Wg = g_wh + (size_t)n0 * K_DIM;

    // gmem->smem cp.async mapping: 256 threads -> (row 0..63, 16B chunk 0..3)
    const int arow = tid >> 2;
    const int achk = tid & 3;
    const uint32_t a_dst = (uint32_t)arow * RSB + achk * 16;
    const __half* a_src = Xg + (size_t)arow * K_DIM + achk * 8;
    const uint32_t b_dst = A_ST_BYTES + (uint32_t)arow * RSB + achk * 16;
    const __half* b_src = Wg + (size_t)arow * K_DIM + achk * 8;

    // ldmatrix lane address components
    const uint32_t lrow = l & 15;
    const uint32_t lkof = (uint32_t)(l >> 4) * 16;
    const uint32_t a_lane = (uint32_t)(wm * 64 + lrow) * RSB + lkof;
    const uint32_t b_lane = A_ST_BYTES + (uint32_t)(wn * 64 + lrow) * RSB + lkof;

    float acc[4][8][4];
#pragma unroll
    for (int a = 0; a < 4; ++a)
#pragma unroll
        for (int b = 0; b < 8; ++b)
#pragma unroll
            for (int c = 0; c < 4; ++c) acc[a][b][c] = 0.f;

    // ---- pipeline prologue: load stages 0..2 ----
#pragma unroll
    for (int s = 0; s < NSTAGE - 1; ++s) {
        const uint32_t sa = sb0 + s * STAGE_BYTES;
        CP_ASYNC16(sa + a_dst, a_src + s * BK);
        CP_ASYNC16(sa + a_dst + 64 * RSB, a_src + (size_t)64 * K_DIM + s * BK);
#pragma unroll
        for (int i = 0; i < 4; ++i)
            CP_ASYNC16(sa + b_dst + (uint32_t)i * 64 * RSB,
                       b_src + (size_t)i * 64 * K_DIM + s * BK);
        CP_COMMIT();
    }
    CP_WAIT(NSTAGE - 2);
    __syncthreads();

    uint32_t fa[2][4][4], fb[2][4][4];

    // fragments for stage 0, ks 0
#pragma unroll
    for (int mi = 0; mi < 4; ++mi)
        LDSM_X4(fa[0][mi], sb0 + a_lane + (uint32_t)mi * 16 * RSB);
#pragma unroll
    for (int bi = 0; bi < 4; ++bi)
        LDSM_X4(fb[0][bi], sb0 + b_lane + (uint32_t)bi * 16 * RSB);

    // ---- main loop ----
    for (int kt = 0; kt < NT; ++kt) {
        const uint32_t sa = sb0 + (kt & (NSTAGE - 1)) * STAGE_BYTES;

        // issue gmem->smem for stage kt+3
        const int nk = kt + NSTAGE - 1;
        if (nk < NT) {
            const uint32_t sn = sb0 + (nk & (NSTAGE - 1)) * STAGE_BYTES;
            CP_ASYNC16(sn + a_dst, a_src + nk * BK);
            CP_ASYNC16(sn + a_dst + 64 * RSB, a_src + (size_t)64 * K_DIM + nk * BK);
#pragma unroll
            for (int i = 0; i < 4; ++i)
                CP_ASYNC16(sn + b_dst + (uint32_t)i * 64 * RSB,
                           b_src + (size_t)i * 64 * K_DIM + nk * BK);
        }
        CP_COMMIT();

        // load ks1 fragments (same stage), then MMA ks0
#pragma unroll
        for (int mi = 0; mi < 4; ++mi)
            LDSM_X4(fa[1][mi], sa + a_lane + (uint32_t)mi * 16 * RSB + 32);
#pragma unroll
        for (int bi = 0; bi < 4; ++bi)
            LDSM_X4(fb[1][bi], sa + b_lane + (uint32_t)bi * 16 * RSB + 32);
#pragma unroll
        for (int mi = 0; mi < 4; ++mi)
#pragma unroll
            for (int bi = 0; bi < 4; ++bi) {
                MMA_F16(acc[mi][2 * bi],     fa[0][mi], fb[0][bi][0], fb[0][bi][2]);
                MMA_F16(acc[mi][2 * bi + 1], fa[0][mi], fb[0][bi][1], fb[0][bi][3]);
            }

        // stage kt+1 is resident after this wait
        CP_WAIT(NSTAGE - 2);
        __syncthreads();

        // prefetch next stage ks0 fragments, then MMA ks1
        const uint32_t sx = sb0 + ((kt + 1) & (NSTAGE - 1)) * STAGE_BYTES;
#pragma unroll
        for (int mi = 0; mi < 4; ++mi)
            LDSM_X4(fa[0][mi], sx + a_lane + (uint32_t)mi * 16 * RSB);
#pragma unroll
        for (int bi = 0; bi < 4; ++bi)
            LDSM_X4(fb[0][bi], sx + b_lane + (uint32_t)bi * 16 * RSB);
#pragma unroll
        for (int mi = 0; mi < 4; ++mi)
#pragma unroll
            for (int bi = 0; bi < 4; ++bi) {
                MMA_F16(acc[mi][2 * bi],     fa[1][mi], fb[1][bi][0], fb[1][bi][2]);
                MMA_F16(acc[mi][2 * bi + 1], fa[1][mi], fb[1][bi][1], fb[1][bi][3]);
            }
    }

    // ---- epilogue: add bias, write fp32 ----
    const int g = l >> 2;
    const int t = l & 3;
#pragma unroll
    for (int mi = 0; mi < 4; ++mi) {
        const int row0 = m0 + wm * 64 + mi * 16 + g;
        float* y0 = Y + (size_t)row0 * N_DIM;
#pragma unroll
        for (int ni = 0; ni < 8; ++ni) {
            const int col = n0 + wn * 64 + (ni >> 1) * 16 + (ni & 1) * 8 + 2 * t;
            const float2 bv = *(const float2*)(bias + col);
            float2 o0, o1;
            o0.x = acc[mi][ni][0] + bv.x;  o0.y = acc[mi][ni][1] + bv.y;
            o1.x = acc[mi][ni][2] + bv.x;  o1.y = acc[mi][ni][3] + bv.y;
            *(float2*)(y0 + col) = o0;
            *(float2*)(y0 + (size_t)8 * N_DIM + col) = o1;   // rows g+8
        }
    }
}

// ---------------------------------------------------------------------------
extern "C" void kernel_launch(void* const* d_in, const int* in_sizes, int n_in,
                              void* d_out, int out_size) {
    const float* x      = (const float*)d_in[0];
    const float* W      = (const float*)d_in[1];
    const float* bias   = (const float*)d_in[2];
    const float* w1a    = (const float*)d_in[3];
    const float* w1b    = (const float*)d_in[4];
    const float* w2a    = (const float*)d_in[5];
    const float* w2b    = (const float*)d_in[6];
    const float* scalar = (const float*)d_in[7];
    float* y = (float*)d_out;

    prologue_kernel<<<XBLK + WBLK, 256>>>(x, W, w1a, w1b, w2a, w2b, scalar);

    cudaFuncSetAttribute(gemm_f16_kernel,
                         cudaFuncAttributeMaxDynamicSharedMemorySize, SMEM_TOTAL);
    const int nblocks = (M_DIM / BM) * (N_DIM / BN);   // 1024
    gemm_f16_kernel<<<nblocks, 256, SMEM_TOTAL>>>(bias, y);
}